// round 9
// baseline (speedup 1.0000x reference)
#include <cuda_runtime.h>

// x <- gelu(x + depthwise_conv3d_3x3x3(x)) x8.  [4,32,64,64,64] fp32.
// ONE kernel: 8 steps fused via cluster(4) sync; per-(b,c) volume stays L2-resident.

#define CC    32
#define VOL   (64*64*64)
#define RS    72                 // words per slab row
#define RSB   (RS*4)             // bytes per slab row
#define SLW   (18*RS)            // words per copy (18 rows)
#define SLW4  (SLW*4)            // bytes per copy
#define PAIRW (4*SLW)            // words per buffer: 2 planes x (copyA+copyB)
#define PAIR4 (PAIRW*4)          // bytes per buffer

typedef unsigned long long u64;
typedef unsigned int u32;

// Ping-pong scratches (last window of each step skips prefetch -> no padding).
__device__ float  g_sA[4 * CC * VOL];
__device__ float  g_sB[4 * CC * VOL];
__device__ __align__(16) float4 g_zero4 = {0.f, 0.f, 0.f, 0.f};

// ---------- packed f32x2 helpers ----------
__device__ __forceinline__ u64 pack2(float lo, float hi) {
    u64 r; asm("mov.b64 %0, {%1, %2};" : "=l"(r) : "f"(lo), "f"(hi)); return r;
}
__device__ __forceinline__ void unpack2(u64 v, float& lo, float& hi) {
    asm("mov.b64 {%0, %1}, %2;" : "=f"(lo), "=f"(hi) : "l"(v));
}
__device__ __forceinline__ void fma2(u64& acc, u64 a, u64 b) {
    asm("fma.rn.f32x2 %0, %1, %2, %0;" : "+l"(acc) : "l"(a), "l"(b));
}
__device__ __forceinline__ void mul2(u64& d, u64 a, u64 b) {
    asm("mul.rn.f32x2 %0, %1, %2;" : "=l"(d) : "l"(a), "l"(b));
}
__device__ __forceinline__ u64 add2(u64 a, u64 b) {
    u64 r; asm("add.rn.f32x2 %0, %1, %2;" : "=l"(r) : "l"(a), "l"(b)); return r;
}

// ---------- volatile SMEM loads (block CSE / hoisting over barriers) ----------
#define LDSP(x, y, base, IMM)                                            \
    asm volatile("ld.shared.v2.u64 {%0, %1}, [%2+%3];"                   \
                 : "=l"(x), "=l"(y) : "r"(base), "n"(IMM))
#define LDS1(x, base, IMM)                                               \
    asm volatile("ld.shared.u64 %0, [%1+%2];"                            \
                 : "=l"(x) : "r"(base), "n"(IMM))

// Exact-erf GELU via A&S 7.1.26 (abs err ~1.5e-7, tol 1e-3).
__device__ __forceinline__ float gelu_exact(float x) {
    float z = x * 0.70710678118654752440f;
    float a = fabsf(z);
    float d = fmaf(0.3275911f, a, 1.0f);
    float t; asm("rcp.approx.f32 %0, %1;" : "=f"(t) : "f"(d));
    float p = fmaf(t, 1.061405429f, -1.453152027f);
    p = fmaf(t, p, 1.421413741f);
    p = fmaf(t, p, -0.284496736f);
    p = fmaf(t, p, 0.254829592f);
    p = p * t;
    float e; asm("ex2.approx.f32 %0, %1;" : "=f"(e) : "f"(-a * a * 1.4426950408889634f));
    float er = fmaf(-p, e, 1.0f);
    er = copysignf(er, z);
    return 0.5f * fmaf(x, er, x);
}

// Store one 16B chunk into copyA (aligned) and shifted copyB of a plane.
__device__ __forceinline__ void put_pair(float* aA, int off, float4 v) {
    *(float4*)(aA + off) = v;
    float* aB = aA + off + SLW + 1;
    aB[0] = v.x;
    *(float2*)(aB + 1) = make_float2(v.y, v.z);
    aB[3] = v.w;
}

// One ky-row of one plane (byte offset SB): windows arrive as aligned u64.
#define ROW(SB, r, X0,X1, Y0,Y1, Z0,Z1, FIRSTZ, CAPC)                            \
    {                                                                            \
        u64 P0, P1, P2, P3, P4;                                                  \
        LDSP(P1, P3, rA, (SB) + (r) * RSB);                                      \
        LDSP(P0, P2, rA, (SB) + SLW4 + (r) * RSB);                               \
        LDS1(P4,     rA, (SB) + SLW4 + (r) * RSB + 16);                          \
        if (CAPC) { cenA0 = P1; cenA1 = P3; }                                    \
        fma2(X0, W2[18 + (r)*3 + 0], P0); fma2(X1, W2[18 + (r)*3 + 0], P2);      \
        fma2(X0, W2[18 + (r)*3 + 1], P1); fma2(X1, W2[18 + (r)*3 + 1], P3);      \
        fma2(X0, W2[18 + (r)*3 + 2], P2); fma2(X1, W2[18 + (r)*3 + 2], P4);      \
        fma2(Y0, W2[ 9 + (r)*3 + 0], P0); fma2(Y1, W2[ 9 + (r)*3 + 0], P2);      \
        fma2(Y0, W2[ 9 + (r)*3 + 1], P1); fma2(Y1, W2[ 9 + (r)*3 + 1], P3);      \
        fma2(Y0, W2[ 9 + (r)*3 + 2], P2); fma2(Y1, W2[ 9 + (r)*3 + 2], P4);      \
        if (FIRSTZ) { mul2(Z0, W2[(r)*3 + 0], P0); mul2(Z1, W2[(r)*3 + 0], P2);} \
        else        { fma2(Z0, W2[(r)*3 + 0], P0); fma2(Z1, W2[(r)*3 + 0], P2);} \
        fma2(Z0, W2[(r)*3 + 1], P1); fma2(Z1, W2[(r)*3 + 1], P3);                \
        fma2(Z0, W2[(r)*3 + 2], P2); fma2(Z1, W2[(r)*3 + 2], P4);                \
    }

#define STORE4(ACC0, ACC1, C0, C1, PTR)                                          \
    {                                                                            \
        u64 u0 = add2(ACC0, C0), u1 = add2(ACC1, C1);                            \
        float o0, o1, o2, o3;                                                    \
        unpack2(u0, o0, o1); unpack2(u1, o2, o3);                                \
        float4 ov = make_float4(gelu_exact(o0), gelu_exact(o1),                  \
                                gelu_exact(o2), gelu_exact(o3));                 \
        *(float4*)(PTR) = ov;                                                    \
    }

// Window k: planes p=2k, p+1. STS pair, prefetch pair k+1, ONE bar, 6 rows, 2 stores.
#define WINDOW(SB, WOFF, A0,A1, B0,B1, C0,C1, D0,D1, DOST0, DOPF)                \
    do {                                                                         \
        put_pair(aA, (WOFF),                 va0);                               \
        put_pair(aA, (WOFF) + 2*SLW,         va1);                               \
        if (tid < 32) {                                                          \
            put_pair(aA, (WOFF) + 16*RS,         vb0);                           \
            put_pair(aA, (WOFF) + 2*SLW + 16*RS, vb1);                           \
        }                                                                        \
        if (DOPF) {                                                              \
            va0 = __ldg(pA); va1 = __ldg(pA + stP); pA += 2 * stP;               \
            if (tid < 32) { vb0 = __ldg(pB); vb1 = __ldg(pB + stQ);              \
                            pB += 2 * stQ; }                                     \
        }                                                                        \
        __syncthreads();                                                         \
        ROW((SB),            0, A0,A1, B0,B1, C0,C1, true,  false)               \
        ROW((SB),            1, A0,A1, B0,B1, C0,C1, false, false)               \
        ROW((SB),            2, A0,A1, B0,B1, C0,C1, false, false)               \
        if (DOST0) STORE4(A0, A1, cenA0, cenA1, optr);                           \
        ROW((SB) + 2*SLW4,   0, B0,B1, C0,C1, D0,D1, true,  false)               \
        ROW((SB) + 2*SLW4,   1, B0,B1, C0,C1, D0,D1, false, true)                \
        ROW((SB) + 2*SLW4,   2, B0,B1, C0,C1, D0,D1, false, false)               \
        {                                                                        \
            u64 c01, c23;                                                        \
            LDSP(c01, c23, rA, (SB) + RSB);                                      \
            STORE4(B0, B1, c01, c23, optr + 4096);                               \
        }                                                                        \
        optr += 8192;                                                            \
    } while (0)

// Cluster of 4 = the 4 H-chunks of one (b,c). Halos only cross H-chunks,
// so cluster-scope sync between steps is exactly sufficient.
__global__ void __launch_bounds__(256, 2) __cluster_dims__(4, 1, 1)
fused_kernel(const float* __restrict__ x, float* __restrict__ outF,
             const float* __restrict__ wts,
             float* __restrict__ sA, float* __restrict__ sB)
{
    const int tx  = threadIdx.x;             // 0..15 (w quads)
    const int ty  = threadIdx.y;             // 0..15 (h rows)
    const int tid = ty * 16 + tx;
    const int h0  = blockIdx.x * 16;
    const int c   = blockIdx.y;
    const int b   = blockIdx.z;
    const size_t volOff = (size_t)(b * CC + c) * VOL;

    // 27 weights duplicated into f32x2 register pairs (same for all steps).
    u64 W2[27];
#pragma unroll
    for (int i = 0; i < 27; ++i) {
        float w = __ldg(&wts[c * 27 + i]);
        W2[i] = pack2(w, w);
    }

    __shared__ __align__(16) float sl[2 * PAIRW];

    // Zero all W-halo words once (data words rewritten every window).
    for (int i = tid; i < 288; i += 256) {
        int buf = i / 144, r1 = i % 144;
        int q   = r1 / 72,  j  = r1 % 72;
        int cp  = j / 36,   k2 = j % 36;
        int row = k2 % 18,  hi = k2 / 18;
        int word = cp ? (hi ? 69 : 4) : (hi ? 68 : 3);
        sl[buf * PAIRW + q * 2 * SLW + cp * SLW + row * RS + word] = 0.f;
    }

    const u32 sbase = (u32)__cvta_generic_to_shared(sl);
    const u32 rA    = sbase + (ty * RS + 4 + 4 * tx) * 4;

    // Loader geometry (constant across steps).
    const int r0 = tid >> 4, cq = tid & 15;
    const int gh0 = h0 - 1 + r0;
    const bool v0 = (gh0 >= 0) && (gh0 < 64);
    const int ofsA = gh0 * 16 + cq;          // float4 units within volume
    const int stP = v0 ? 1024 : 0;

    const int gh1 = h0 + 15 + r0;
    const bool v1 = (tid < 32) && (gh1 < 64);
    const int ofsB = gh1 * 16 + cq;
    const int stQ = v1 ? 1024 : 0;

    float* aA = sl + (r0 * RS + 4 + 4 * cq);
    const int outOfs = (h0 + ty) * 64 + 4 * tx;

    const float* sin = x;                    // step-0 input

#pragma unroll 1
    for (int s = 0; s < 8; ++s) {
        float* sout = (s == 7) ? outF : ((s & 1) ? sB : sA);

        const float* vin = sin + volOff;
        const float4* pA = v0 ? (const float4*)vin + ofsA : &g_zero4;
        const float4* pB = v1 ? (const float4*)vin + ofsB : &g_zero4;
        float* optr = (sout + volOff) + outOfs - 4096;

        // Prologue: load plane pair 0.
        float4 va0 = __ldg(pA), va1 = __ldg(pA + stP); pA += 2 * stP;
        float4 vb0 = make_float4(0.f, 0.f, 0.f, 0.f), vb1 = vb0;
        if (tid < 32) { vb0 = __ldg(pB); vb1 = __ldg(pB + stQ); pB += 2 * stQ; }

        u64 a00=0,a01=0, a10=0,a11=0, a20=0,a21=0, a30=0,a31=0;
        u64 cenA0=0, cenA1=0;

        WINDOW(0,     0,     a00,a01, a10,a11, a20,a21, a30,a31, false, true);  // w0
        WINDOW(PAIR4, PAIRW, a20,a21, a30,a31, a00,a01, a10,a11, true,  true);  // w1
#pragma unroll 1
        for (int i = 0; i < 14; ++i) {                                          // w2..w29
            WINDOW(0,     0,     a00,a01, a10,a11, a20,a21, a30,a31, true, true);
            WINDOW(PAIR4, PAIRW, a20,a21, a30,a31, a00,a01, a10,a11, true, true);
        }
        WINDOW(0,     0,     a00,a01, a10,a11, a20,a21, a30,a31, true, true);   // w30
        WINDOW(PAIR4, PAIRW, a20,a21, a30,a31, a00,a01, a10,a11, true, false);  // w31

        // out(63): partial in a0, center from w31's plane-63 capture.
        STORE4(a00, a01, cenA0, cenA1, optr);

        // Make this step's stores visible to cluster peers, then sync cluster
        // (superset of __syncthreads; flushes L1D per sm_103a behavior).
        if (s < 7) {
            __threadfence();
            asm volatile("barrier.cluster.arrive.aligned;" ::: "memory");
            asm volatile("barrier.cluster.wait.aligned;"   ::: "memory");
        }
        sin = sout;
    }
}

extern "C" void kernel_launch(void* const* d_in, const int* in_sizes, int n_in,
                              void* d_out, int out_size)
{
    const float* x = (const float*)d_in[0];
    const float* w = (const float*)d_in[1];
    float* out = (float*)d_out;

    float *sA = nullptr, *sB = nullptr;
    cudaGetSymbolAddress((void**)&sA, g_sA);
    cudaGetSymbolAddress((void**)&sB, g_sB);

    dim3 grid(4, CC, 4);    // x-dim (H-chunks) grouped into clusters of 4
    dim3 blk(16, 16);
    fused_kernel<<<grid, blk>>>(x, out, w, sA, sB);
}

// round 10
// speedup vs baseline: 1.0414x; 1.0414x over previous
#include <cuda_runtime.h>

// x <- gelu(x + depthwise_conv3d_3x3x3(x)) x8.  [4,32,64,64,64] fp32.
// Fused 8-step cluster kernel; 128 threads; 2 output H-rows per thread;
// cp.async loader; single-copy slabs; 3 rotating plane buffers.

#define CC    32
#define VOL   (64*64*64)
#define RS    72                 // words per slab row
#define RSB   (RS*4)             // 288 bytes per row
#define BUFB  (18*RSB)           // 5184 bytes per plane buffer

typedef unsigned long long u64;
typedef unsigned int u32;

__device__ float  g_sA[4 * CC * VOL];
__device__ float  g_sB[4 * CC * VOL];
__device__ __align__(16) float4 g_zero4 = {0.f, 0.f, 0.f, 0.f};

// ---------- packed f32x2 helpers ----------
__device__ __forceinline__ u64 pack2(float lo, float hi) {
    u64 r; asm("mov.b64 %0, {%1, %2};" : "=l"(r) : "f"(lo), "f"(hi)); return r;
}
__device__ __forceinline__ void unpack2(u64 v, float& lo, float& hi) {
    asm("mov.b64 {%0, %1}, %2;" : "=f"(lo), "=f"(hi) : "l"(v));
}
__device__ __forceinline__ void fma2(u64& acc, u64 a, u64 b) {
    asm("fma.rn.f32x2 %0, %1, %2, %0;" : "+l"(acc) : "l"(a), "l"(b));
}
__device__ __forceinline__ void mul2(u64& d, u64 a, u64 b) {
    asm("mul.rn.f32x2 %0, %1, %2;" : "=l"(d) : "l"(a), "l"(b));
}
__device__ __forceinline__ u64 add2(u64 a, u64 b) {
    u64 r; asm("add.rn.f32x2 %0, %1, %2;" : "=l"(r) : "l"(a), "l"(b)); return r;
}

// ---------- volatile SMEM loads (no CSE across planes / no hoist over bars) ----------
#define LDSP(x, y, base, IMM)                                            \
    asm volatile("ld.shared.v2.u64 {%0, %1}, [%2+%3];"                   \
                 : "=l"(x), "=l"(y) : "r"(base), "n"(IMM))

// ---------- cp.async ----------
#define CPA16(dst, src)                                                  \
    asm volatile("cp.async.cg.shared.global [%0], [%1], 16;"             \
                 :: "r"(dst), "l"(src))
#define CPA16P(pred, dst, src)                                           \
    asm volatile("{ .reg .pred p; setp.ne.s32 p, %0, 0;"                 \
                 "  @p cp.async.cg.shared.global [%1], [%2], 16; }"      \
                 :: "r"(pred), "r"(dst), "l"(src))
#define CPCOMMIT() asm volatile("cp.async.commit_group;")
#define CPWAIT0()  asm volatile("cp.async.wait_group 0;")

// Exact-erf GELU via A&S 7.1.26 (abs err ~1.5e-7, tol 1e-3).
__device__ __forceinline__ float gelu_exact(float x) {
    float z = x * 0.70710678118654752440f;
    float a = fabsf(z);
    float d = fmaf(0.3275911f, a, 1.0f);
    float t; asm("rcp.approx.f32 %0, %1;" : "=f"(t) : "f"(d));
    float p = fmaf(t, 1.061405429f, -1.453152027f);
    p = fmaf(t, p, 1.421413741f);
    p = fmaf(t, p, -0.284496736f);
    p = fmaf(t, p, 0.254829592f);
    p = p * t;
    float e; asm("ex2.approx.f32 %0, %1;" : "=f"(e) : "f"(-a * a * 1.4426950408889634f));
    float er = fmaf(-p, e, 1.0f);
    er = copysignf(er, z);
    return 0.5f * fmaf(x, er, x);
}

// Load one input row's 5 stencil windows as u64 pairs using 3 conflict-free
// LDS.128 (words 4tx..+3 / +4..+7 / +8..+11 of the row) + ALU assembly.
#define LOADQ(OFF)                                                       \
    u64 E0, E1, Q1, Q3, F0, F1;                                          \
    LDSP(E0, E1, rB, (OFF));                                             \
    LDSP(Q1, Q3, rB, (OFF) + 16);                                        \
    LDSP(F0, F1, rB, (OFF) + 32);                                        \
    float fm, fp, f0, f1, f2, f3, dm0, dm1;                              \
    unpack2(E1, dm0, fm);                                                \
    unpack2(F0, fp, dm1);                                                \
    unpack2(Q1, f0, f1);                                                 \
    unpack2(Q3, f2, f3);                                                 \
    u64 Q0 = pack2(fm, f0), Q2 = pack2(f1, f2), Q4 = pack2(f3, fp);      \
    (void)E0; (void)F1; (void)dm0; (void)dm1;

#define FMA6(S0, S1, WB)                                                 \
    fma2(S0, W2[(WB)+0], Q0); fma2(S1, W2[(WB)+0], Q2);                  \
    fma2(S0, W2[(WB)+1], Q1); fma2(S1, W2[(WB)+1], Q3);                  \
    fma2(S0, W2[(WB)+2], Q2); fma2(S1, W2[(WB)+2], Q4);
#define MUL6(S0, S1, WB)                                                 \
    mul2(S0, W2[(WB)+0], Q0); mul2(S1, W2[(WB)+0], Q2);                  \
    fma2(S0, W2[(WB)+1], Q1); fma2(S1, W2[(WB)+1], Q3);                  \
    fma2(S0, W2[(WB)+2], Q2); fma2(S1, W2[(WB)+2], Q4);

#define STORE4(A0, A1, C0, C1, PTR)                                      \
    {                                                                    \
        u64 u0 = add2(A0, C0), u1 = add2(A1, C1);                        \
        float o0, o1, o2, o3;                                            \
        unpack2(u0, o0, o1); unpack2(u1, o2, o3);                        \
        float4 ov = make_float4(gelu_exact(o0), gelu_exact(o1),          \
                                gelu_exact(o2), gelu_exact(o3));         \
        *(float4*)(PTR) = ov;                                            \
    }

// Window p: wait plane p's cp.async, barrier, issue cp.async p+1 (disjoint buf),
// compute 4 input rows (2 output rows x 3 pipeline stages), store out(p-1).
// X completes out(p-1) [kz2], Y = out(p) [kz1], Z = out(p+1) fresh [kz0].
// X0,X1 = output row R0 halves; X2,X3 = row R1 (same for Y,Z).
#define WINDOW(SB, SBN, SBC, X0,X1,X2,X3, Y0,Y1,Y2,Y3, Z0,Z1,Z2,Z3, DOST, DOPF) \
    do {                                                                 \
        CPWAIT0();                                                       \
        __syncthreads();                                                 \
        if (DOPF) {                                                      \
            CPA16(d0 + (SBN), p0); CPA16(d1 + (SBN), p1);                \
            CPA16P(isB, d2 + (SBN), p2);                                 \
            CPCOMMIT();                                                  \
            p0 += st0; p1 += st1; p2 += st2;                             \
        }                                                                \
        u64 c0, c1, c2, c3;                                              \
        if (DOST) {                                                      \
            LDSP(c0, c1, rB, (SBC) + RSB + 16);                          \
            LDSP(c2, c3, rB, (SBC) + 2 * RSB + 16);                      \
        }                                                                \
        { LOADQ((SB))           MUL6(Z0,Z1,0)  FMA6(Y0,Y1,9)   FMA6(X0,X1,18) }  \
        { LOADQ((SB) + RSB)     FMA6(Z0,Z1,3)  FMA6(Y0,Y1,12)  FMA6(X0,X1,21)    \
                                MUL6(Z2,Z3,0)  FMA6(Y2,Y3,9)   FMA6(X2,X3,18) }  \
        { LOADQ((SB) + 2*RSB)   FMA6(Z0,Z1,6)  FMA6(Y0,Y1,15)  FMA6(X0,X1,24)    \
                                FMA6(Z2,Z3,3)  FMA6(Y2,Y3,12)  FMA6(X2,X3,21) }  \
        { LOADQ((SB) + 3*RSB)   FMA6(Z2,Z3,6)  FMA6(Y2,Y3,15)  FMA6(X2,X3,24) }  \
        if (DOST) {                                                      \
            STORE4(X0, X1, c0, c1, optr);                                \
            STORE4(X2, X3, c2, c3, optr + 64);                           \
            optr += 4096;                                                \
        }                                                                \
    } while (0)

// Cluster of 4 = the 4 H-chunks of one (b,c); halos only cross H-chunks.
__global__ void __launch_bounds__(128, 4) __cluster_dims__(4, 1, 1)
fused_kernel(const float* __restrict__ x, float* __restrict__ outF,
             const float* __restrict__ wts,
             float* __restrict__ sA, float* __restrict__ sB)
{
    const int tid = threadIdx.x;             // 0..127
    const int tx  = tid & 15;                // w quad
    const int ty  = tid >> 4;                // 0..7: output rows 2ty, 2ty+1
    const int h0  = blockIdx.x * 16;
    const int c   = blockIdx.y;
    const int b   = blockIdx.z;
    const size_t volOff = (size_t)(b * CC + c) * VOL;

    u64 W2[27];
#pragma unroll
    for (int i = 0; i < 27; ++i) {
        float w = __ldg(&wts[c * 27 + i]);
        W2[i] = pack2(w, w);
    }

    // 3 rotating plane buffers; row: words 0..2 pad, 3 = left halo(0),
    // 4..67 data, 68 = right halo(0), 69..71 pad.
    __shared__ __align__(16) float sl[3 * 18 * RS];

    if (tid < 108) {                         // zero halo words once
        int buf = tid / 36, k = tid % 36;
        sl[buf * (18 * RS) + (k % 18) * RS + (k < 18 ? 3 : 68)] = 0.f;
    }

    const u32 sbase = (u32)__cvta_generic_to_shared(sl);
    const u32 rB    = sbase + ty * 2 * RSB + 16 * tx;   // word 4tx of row 2ty

    // Loader: thread covers 16B chunks of rows lr, lr+8, (tid<32: lr+16).
    const int lr = tid >> 4, lq = tid & 15;
    const int gh0 = h0 - 1 + lr;
    const int gh1 = gh0 + 8;
    const int gh2 = gh0 + 16;
    const bool v0 = (gh0 >= 0) && (gh0 < 64);
    const bool v1 = (gh1 < 64);                         // gh1 >= 7 always
    const bool v2 = (tid < 32) && (gh2 < 64);
    const int isB = (tid < 32) ? 1 : 0;
    const int of0 = gh0 * 16 + lq, of1 = gh1 * 16 + lq, of2 = gh2 * 16 + lq;
    const int st0 = v0 ? 1024 : 0, st1 = v1 ? 1024 : 0, st2 = v2 ? 1024 : 0;

    const u32 d0 = sbase + (lr * RS + 4 + 4 * lq) * 4;
    const u32 d1 = d0 + 8 * RSB;
    const u32 d2 = d0 + 16 * RSB;

    const int outOfs = (h0 + 2 * ty) * 64 + 4 * tx;

    const float* sin = x;

#pragma unroll 1
    for (int s = 0; s < 8; ++s) {
        float* sout = (s == 7) ? outF : ((s & 1) ? sB : sA);
        const float* vin = sin + volOff;

        const float4* p0 = v0 ? (const float4*)vin + of0 : &g_zero4;
        const float4* p1 = v1 ? (const float4*)vin + of1 : &g_zero4;
        const float4* p2 = v2 ? (const float4*)vin + of2 : &g_zero4;
        float* optr = (sout + volOff) + outOfs;

        // Prologue: plane 0 -> buf0.
        CPA16(d0, p0); CPA16(d1, p1); CPA16P(isB, d2, p2);
        CPCOMMIT();
        p0 += st0; p1 += st1; p2 += st2;

        // s0..s2 role quads (out-row0 h0,h1, out-row1 h0,h1).
        u64 s00=0,s01=0,s02=0,s03=0, s10=0,s11=0,s12=0,s13=0,
            s20=0,s21=0,s22=0,s23=0;

        // Window p: X=s[(p+2)%3], Y=s[p%3], Z=s[(p+1)%3]; bufs SB=p%3 etc.
        WINDOW(0, BUFB, 2*BUFB, s20,s21,s22,s23, s00,s01,s02,s03,
               s10,s11,s12,s13, false, true);                        // p=0
#pragma unroll 1
        for (int i = 0; i < 20; ++i) {                               // p=1..60
            WINDOW(BUFB, 2*BUFB, 0, s00,s01,s02,s03, s10,s11,s12,s13,
                   s20,s21,s22,s23, true, true);                     // p%3==1
            WINDOW(2*BUFB, 0, BUFB, s10,s11,s12,s13, s20,s21,s22,s23,
                   s00,s01,s02,s03, true, true);                     // p%3==2
            WINDOW(0, BUFB, 2*BUFB, s20,s21,s22,s23, s00,s01,s02,s03,
                   s10,s11,s12,s13, true, true);                     // p%3==0
        }
        WINDOW(BUFB, 2*BUFB, 0, s00,s01,s02,s03, s10,s11,s12,s13,
               s20,s21,s22,s23, true, true);                         // p=61
        WINDOW(2*BUFB, 0, BUFB, s10,s11,s12,s13, s20,s21,s22,s23,
               s00,s01,s02,s03, true, true);                         // p=62
        WINDOW(0, BUFB, 2*BUFB, s20,s21,s22,s23, s00,s01,s02,s03,
               s10,s11,s12,s13, true, false);                        // p=63

        // out(63): kz2 (plane 64) = 0; partial = Y of window 63 = s0;
        // centers = plane 63 (buf0) rows 2ty+1, 2ty+2.
        {
            u64 c0, c1, c2, c3;
            LDSP(c0, c1, rB, RSB + 16);
            LDSP(c2, c3, rB, 2 * RSB + 16);
            STORE4(s00, s01, c0, c1, optr);
            STORE4(s02, s03, c2, c3, optr + 64);
        }

        if (s < 7) {
            __threadfence();
            asm volatile("barrier.cluster.arrive.aligned;" ::: "memory");
            asm volatile("barrier.cluster.wait.aligned;"   ::: "memory");
        }
        sin = sout;
    }
}

extern "C" void kernel_launch(void* const* d_in, const int* in_sizes, int n_in,
                              void* d_out, int out_size)
{
    const float* x = (const float*)d_in[0];
    const float* w = (const float*)d_in[1];
    float* out = (float*)d_out;

    float *sA = nullptr, *sB = nullptr;
    cudaGetSymbolAddress((void**)&sA, g_sA);
    cudaGetSymbolAddress((void**)&sB, g_sB);

    dim3 grid(4, CC, 4);    // x-dim (H-chunks) grouped into clusters of 4
    dim3 blk(128);
    fused_kernel<<<grid, blk>>>(x, out, w, sA, sB);
}